// round 4
// baseline (speedup 1.0000x reference)
#include <cuda_runtime.h>
#include <cstdint>

namespace {

constexpr int Bsz = 512, Msl = 32, DIN = 1024, DH = 4096, DOUT = 1024;
constexpr int BM = 128, BN = 128, BK = 32;
constexpr int TILE_B = 128 * BK * 4;      // 16 KB per operand tile
constexpr int STAGE  = 2 * TILE_B;        // A + B = 32 KB
constexpr int SMEM_DYN = 2 * STAGE;       // 2-stage ping-pong = 64 KB

// Intermediate h: [m][b][dh]
__device__ float g_h[(size_t)Bsz * Msl * DH];

__device__ __forceinline__ uint32_t f2tf(float f) {
    uint32_t u; asm("cvt.rna.tf32.f32 %0, %1;" : "=r"(u) : "f"(f)); return u;
}
__device__ __forceinline__ uint32_t smem_u32(const void* p) {
    uint32_t a;
    asm("{ .reg .u64 t; cvta.to.shared.u64 t, %1; cvt.u32.u64 %0, t; }" : "=r"(a) : "l"(p));
    return a;
}
__device__ __forceinline__ void ldsm4(uint32_t r[4], uint32_t addr) {
    asm volatile("ldmatrix.sync.aligned.m8n8.x4.shared.b16 {%0,%1,%2,%3}, [%4];"
                 : "=r"(r[0]), "=r"(r[1]), "=r"(r[2]), "=r"(r[3]) : "r"(addr));
}
__device__ __forceinline__ void mma_tf32(float acc[4], const uint32_t a[4],
                                         uint32_t b0, uint32_t b1) {
    asm volatile(
        "mma.sync.aligned.m16n8k8.row.col.f32.tf32.tf32.f32 "
        "{%0,%1,%2,%3}, {%4,%5,%6,%7}, {%8,%9}, {%0,%1,%2,%3};\n"
        : "+f"(acc[0]), "+f"(acc[1]), "+f"(acc[2]), "+f"(acc[3])
        : "r"(a[0]), "r"(a[1]), "r"(a[2]), "r"(a[3]), "r"(b0), "r"(b1));
}

// C[BM,BN] tile of A[*,K] x W[K,*] (+bias, optional ReLU), batched over blockIdx.z.
// A rows are K-contiguous (stride lda). W rows are n-contiguous (stride ldw).
// Smem: A as [m][k] K-major xor-swizzled, B as [n][k] K-major xor-swizzled
// (W transposed 4x4 in registers on the way in).
template<bool RELU>
__global__ void __launch_bounds__(256, 2)
gemm_tf32(const float* __restrict__ Ag, const float* __restrict__ Wg,
          const float* __restrict__ biasg, float* __restrict__ Cg,
          int K,
          long aBatch, int lda, long wBatch, int ldw,
          long biasBatch, long cBatch, int ldc)
{
    extern __shared__ char sm[];
    const uint32_t sb = smem_u32(sm);

    const int tid  = threadIdx.x;
    const int lane = tid & 31, warp = tid >> 5;
    const int g = lane >> 2, tg = lane & 3;
    const int wm = warp & 3, wn = warp >> 2;          // 4 (m) x 2 (n) warps

    const int m0 = blockIdx.y * BM;
    const int n0 = blockIdx.x * BN;
    const float* A    = Ag    + (size_t)blockIdx.z * aBatch;
    const float* W    = Wg    + (size_t)blockIdx.z * wBatch;
    const float* bias = biasg + (size_t)blockIdx.z * biasBatch;
    float*       C    = Cg    + (size_t)blockIdx.z * cBatch;

    // LDG assignments.
    // A: row-major K-contiguous, same as before.
    const int a_kg = tid & 7;          // 16B group within 128B k-row
    const int a_r0 = tid >> 3;         // row r0 (+32 per it)
    // B: k-group varies WITHIN the warp so the transposed STS covers all
    // 8 bank slots per lane-quarter (conflict-free), n-group varies across.
    const int b_k0 = (tid & 7) * 4;    // k base of 4x4 block (0..28)
    const int b_n  = (tid >> 3) * 4;   // n base of this thread's 4x4 block

    // ldmatrix per-thread pieces
    const int lrow = lane & 15;
    const int lkh  = (lane >> 4) << 4;  // 0 or 16 bytes (k half)

    float acc[2][8][4];
    #pragma unroll
    for (int i = 0; i < 2; i++)
        #pragma unroll
        for (int j = 0; j < 8; j++)
            #pragma unroll
            for (int q = 0; q < 4; q++) acc[i][j][q] = 0.f;

    float4 ra[4], rb[4];

    auto ldgA = [&](int k0) {
        #pragma unroll
        for (int it = 0; it < 4; ++it) {
            const int r = a_r0 + it * 32;
            ra[it] = *(const float4*)(A + (size_t)(m0 + r) * lda + k0 + a_kg * 4);
        }
    };
    auto ldgB = [&](int k0) {
        const float* wp = W + (size_t)(k0 + b_k0) * ldw + n0 + b_n;
        #pragma unroll
        for (int j = 0; j < 4; ++j)
            rb[j] = *(const float4*)(wp + (size_t)j * ldw);
    };
    auto stsA = [&](int buf) {
        const uint32_t base = buf * STAGE;
        #pragma unroll
        for (int it = 0; it < 4; ++it) {
            const int r = a_r0 + it * 32;
            uint4 u;
            u.x = f2tf(ra[it].x); u.y = f2tf(ra[it].y);
            u.z = f2tf(ra[it].z); u.w = f2tf(ra[it].w);
            const uint32_t off = r * 128 + ((a_kg * 16) ^ ((r & 7) << 4));
            *(uint4*)(sm + base + off) = u;
        }
    };
    auto stsB = [&](int buf) {
        const uint32_t base = buf * STAGE + TILE_B;
        #pragma unroll
        for (int j = 0; j < 4; ++j) {           // j: n offset within the 4x4 block
            uint4 c;
            c.x = f2tf(j == 0 ? rb[0].x : j == 1 ? rb[0].y : j == 2 ? rb[0].z : rb[0].w);
            c.y = f2tf(j == 0 ? rb[1].x : j == 1 ? rb[1].y : j == 2 ? rb[1].z : rb[1].w);
            c.z = f2tf(j == 0 ? rb[2].x : j == 1 ? rb[2].y : j == 2 ? rb[2].z : rb[2].w);
            c.w = f2tf(j == 0 ? rb[3].x : j == 1 ? rb[3].y : j == 2 ? rb[3].z : rb[3].w);
            const int row = b_n + j;            // n row in smem
            const uint32_t off = row * 128 + ((b_k0 * 4) ^ ((row & 7) << 4));
            *(uint4*)(sm + base + off) = c;
        }
    };

    auto compute = [&](int buf) {
        const uint32_t Ab = sb + buf * STAGE;
        const uint32_t Bb = Ab + TILE_B;
        #pragma unroll
        for (int ks = 0; ks < 4; ++ks) {
            const int kb = ks * 32 + lkh;
            uint32_t af[2][4];
            #pragma unroll
            for (int mt = 0; mt < 2; ++mt) {
                const int row = wm * 32 + mt * 16 + lrow;
                ldsm4(af[mt], Ab + row * 128 + (kb ^ ((row & 7) << 4)));
            }
            uint32_t bf[4][4];
            #pragma unroll
            for (int ng = 0; ng < 4; ++ng) {
                const int row = wn * 64 + ng * 16 + lrow;
                ldsm4(bf[ng], Bb + row * 128 + (kb ^ ((row & 7) << 4)));
            }
            #pragma unroll
            for (int mt = 0; mt < 2; ++mt)
                #pragma unroll
                for (int nt = 0; nt < 8; ++nt)
                    mma_tf32(acc[mt][nt], af[mt],
                             bf[nt >> 1][nt & 1], bf[nt >> 1][(nt & 1) + 2]);
        }
    };

    const int S = K / BK;

    ldgA(0); ldgB(0);
    stsA(0); stsB(0);
    __syncthreads();

    #pragma unroll 1
    for (int kt = 0; kt < S; ++kt) {
        const int nxt = kt + 1;
        if (nxt < S) { ldgA(nxt * BK); ldgB(nxt * BK); }
        compute(kt & 1);
        if (nxt < S) { stsA(nxt & 1); stsB(nxt & 1); }
        __syncthreads();
    }

    // epilogue: +bias, optional relu, float2 stores
    #pragma unroll
    for (int mt = 0; mt < 2; ++mt) {
        const int r = m0 + wm * 32 + mt * 16 + g;
        #pragma unroll
        for (int nt = 0; nt < 8; ++nt) {
            const int c = n0 + wn * 64 + nt * 8 + tg * 2;
            const float b0v = bias[c], b1v = bias[c + 1];
            float v0 = acc[mt][nt][0] + b0v;
            float v1 = acc[mt][nt][1] + b1v;
            float v2 = acc[mt][nt][2] + b0v;
            float v3 = acc[mt][nt][3] + b1v;
            if (RELU) {
                v0 = fmaxf(v0, 0.f); v1 = fmaxf(v1, 0.f);
                v2 = fmaxf(v2, 0.f); v3 = fmaxf(v3, 0.f);
            }
            float2 p0; p0.x = v0; p0.y = v1;
            float2 p1; p1.x = v2; p1.y = v3;
            *(float2*)(C + (size_t)r * ldc + c)       = p0;
            *(float2*)(C + (size_t)(r + 8) * ldc + c) = p1;
        }
    }
}

} // anonymous namespace

extern "C" void kernel_launch(void* const* d_in, const int* in_sizes, int n_in,
                              void* d_out, int out_size) {
    (void)in_sizes; (void)n_in; (void)out_size;
    const float* x  = (const float*)d_in[0];  // [B, M, DIN]
    const float* W1 = (const float*)d_in[1];  // [M, DIN, DH]
    const float* b1 = (const float*)d_in[2];  // [M, DH]
    const float* W2 = (const float*)d_in[3];  // [M, DH, DOUT]
    const float* b2 = (const float*)d_in[4];  // [M, DOUT]
    float* out = (float*)d_out;               // [B, M, DOUT]

    float* h = nullptr;
    cudaGetSymbolAddress((void**)&h, g_h);

    cudaFuncSetAttribute(gemm_tf32<true>,  cudaFuncAttributeMaxDynamicSharedMemorySize, SMEM_DYN);
    cudaFuncSetAttribute(gemm_tf32<false>, cudaFuncAttributeMaxDynamicSharedMemorySize, SMEM_DYN);

    dim3 blk(256);

    // Layer 1: per m, h[b, n] = relu(x[b,:] @ W1 + b1)
    dim3 g1(DH / BN, Bsz / BM, Msl);
    gemm_tf32<true><<<g1, blk, SMEM_DYN>>>(
        x, W1, b1, h, DIN,
        /*aBatch*/ (long)DIN,        /*lda*/ Msl * DIN,
        /*wBatch*/ (long)DIN * DH,   /*ldw*/ DH,
        /*biasBatch*/ (long)DH,
        /*cBatch*/ (long)Bsz * DH,   /*ldc*/ DH);

    // Layer 2: per m, out[b, n] = h[b,:] @ W2 + b2
    dim3 g2(DOUT / BN, Bsz / BM, Msl);
    gemm_tf32<false><<<g2, blk, SMEM_DYN>>>(
        h, W2, b2, out, DH,
        /*aBatch*/ (long)Bsz * DH,   /*lda*/ DH,
        /*wBatch*/ (long)DH * DOUT,  /*ldw*/ DOUT,
        /*biasBatch*/ (long)DOUT,
        /*cBatch*/ (long)DOUT,       /*ldc*/ Msl * DOUT);
}

// round 5
// speedup vs baseline: 1.1631x; 1.1631x over previous
#include <cuda_runtime.h>
#include <cstdint>

namespace {

constexpr int Bsz = 512, Msl = 32, DIN = 1024, DH = 4096, DOUT = 1024;
constexpr int BM = 128, BN = 128, BK = 32;
constexpr int TILE_B = 128 * BK * 4;      // 16 KB per operand tile
constexpr int STAGE  = 2 * TILE_B;        // A + B = 32 KB
constexpr int SMEM_DYN = 2 * STAGE;       // 2-stage ping-pong = 64 KB

// Intermediate h: [m][b][dh]
__device__ float g_h[(size_t)Bsz * Msl * DH];

__device__ __forceinline__ uint32_t f2tf(float f) {
    uint32_t u; asm("cvt.rna.tf32.f32 %0, %1;" : "=r"(u) : "f"(f)); return u;
}
__device__ __forceinline__ uint32_t smem_u32(const void* p) {
    uint32_t a;
    asm("{ .reg .u64 t; cvta.to.shared.u64 t, %1; cvt.u32.u64 %0, t; }" : "=r"(a) : "l"(p));
    return a;
}
__device__ __forceinline__ void ldsm4(uint32_t r[4], uint32_t addr) {
    asm volatile("ldmatrix.sync.aligned.m8n8.x4.shared.b16 {%0,%1,%2,%3}, [%4];"
                 : "=r"(r[0]), "=r"(r[1]), "=r"(r[2]), "=r"(r[3]) : "r"(addr));
}
__device__ __forceinline__ void mma_tf32(float acc[4], const uint32_t a[4],
                                         uint32_t b0, uint32_t b1) {
    asm volatile(
        "mma.sync.aligned.m16n8k8.row.col.f32.tf32.tf32.f32 "
        "{%0,%1,%2,%3}, {%4,%5,%6,%7}, {%8,%9}, {%0,%1,%2,%3};\n"
        : "+f"(acc[0]), "+f"(acc[1]), "+f"(acc[2]), "+f"(acc[3])
        : "r"(a[0]), "r"(a[1]), "r"(a[2]), "r"(a[3]), "r"(b0), "r"(b1));
}

// C[BM,BN] tile of A[*,K] x W[K,*] (+bias, optional ReLU), batched over blockIdx.z.
// A rows are K-contiguous (stride lda). W rows are n-contiguous (stride ldw).
// Smem: A as [m][k] K-major xor-swizzled, B as [n][k] K-major xor-swizzled
// (W transposed 4x4 in registers on the way in; store order permuted per lane
// so each 8-lane store phase covers all 8 bank slots).
template<bool RELU>
__global__ void __launch_bounds__(256, 2)
gemm_tf32(const float* __restrict__ Ag, const float* __restrict__ Wg,
          const float* __restrict__ biasg, float* __restrict__ Cg,
          int K,
          long aBatch, int lda, long wBatch, int ldw,
          long biasBatch, long cBatch, int ldc)
{
    extern __shared__ char sm[];
    const uint32_t sb = smem_u32(sm);

    const int tid  = threadIdx.x;
    const int lane = tid & 31, warp = tid >> 5;
    const int g = lane >> 2, tg = lane & 3;
    const int wm = warp & 3, wn = warp >> 2;          // 4 (m) x 2 (n) warps

    const int m0 = blockIdx.y * BM;
    const int n0 = blockIdx.x * BN;
    const float* A    = Ag    + (size_t)blockIdx.z * aBatch;
    const float* W    = Wg    + (size_t)blockIdx.z * wBatch;
    const float* bias = biasg + (size_t)blockIdx.z * biasBatch;
    float*       C    = Cg    + (size_t)blockIdx.z * cBatch;

    // LDG assignments (round-3 proven-coalesced mappings)
    const int a_kg = tid & 7;          // 16B group within 128B k-row
    const int a_r0 = tid >> 3;         // row r0 (+32 per it)
    const int b_n  = (tid & 31) * 4;   // n base of this thread's 4x4 block
    const int b_k0 = (tid >> 5) * 4;   // k base of 4x4 block (warp-constant)

    // ldmatrix per-thread pieces
    const int lrow = lane & 15;
    const int lkh  = (lane >> 4) << 4;  // 0 or 16 bytes (k half)

    float acc[2][8][4];
    #pragma unroll
    for (int i = 0; i < 2; i++)
        #pragma unroll
        for (int j = 0; j < 8; j++)
            #pragma unroll
            for (int q = 0; q < 4; q++) acc[i][j][q] = 0.f;

    float4 ra[4], rb[4];

    auto ldgA = [&](int k0) {
        #pragma unroll
        for (int it = 0; it < 4; ++it) {
            const int r = a_r0 + it * 32;
            ra[it] = *(const float4*)(A + (size_t)(m0 + r) * lda + k0 + a_kg * 4);
        }
    };
    auto ldgB = [&](int k0) {
        const float* wp = W + (size_t)(k0 + b_k0) * ldw + n0 + b_n;
        #pragma unroll
        for (int j = 0; j < 4; ++j)
            rb[j] = *(const float4*)(wp + (size_t)j * ldw);
    };
    auto stsA = [&](int buf) {
        const uint32_t base = buf * STAGE;
        #pragma unroll
        for (int it = 0; it < 4; ++it) {
            const int r = a_r0 + it * 32;
            uint4 u;
            u.x = f2tf(ra[it].x); u.y = f2tf(ra[it].y);
            u.z = f2tf(ra[it].z); u.w = f2tf(ra[it].w);
            const uint32_t off = r * 128 + ((a_kg * 16) ^ ((r & 7) << 4));
            *(uint4*)(sm + base + off) = u;
        }
    };
    // Transpose the 4x4 block in registers, then store n-columns in a
    // lane-dependent order: inst j writes column p = (j + (lane>>1)) & 3,
    // so each 8-lane phase hits all 8 bank slots (row&7 = (lane&1)*4 + p).
    auto stsB = [&](int buf) {
        const uint32_t base = buf * STAGE + TILE_B;
        uint4 c[4];
        c[0].x = f2tf(rb[0].x); c[0].y = f2tf(rb[1].x); c[0].z = f2tf(rb[2].x); c[0].w = f2tf(rb[3].x);
        c[1].x = f2tf(rb[0].y); c[1].y = f2tf(rb[1].y); c[1].z = f2tf(rb[2].y); c[1].w = f2tf(rb[3].y);
        c[2].x = f2tf(rb[0].z); c[2].y = f2tf(rb[1].z); c[2].z = f2tf(rb[2].z); c[2].w = f2tf(rb[3].z);
        c[3].x = f2tf(rb[0].w); c[3].y = f2tf(rb[1].w); c[3].z = f2tf(rb[2].w); c[3].w = f2tf(rb[3].w);
        const int rot = (lane >> 1) & 3;
        #pragma unroll
        for (int j = 0; j < 4; ++j) {
            const int p = (j + rot) & 3;
            const int row = b_n + p;
            const uint32_t off = row * 128 + ((b_k0 * 4) ^ ((row & 7) << 4));
            *(uint4*)(sm + base + off) = c[p];
        }
    };

    auto compute = [&](int buf) {
        const uint32_t Ab = sb + buf * STAGE;
        const uint32_t Bb = Ab + TILE_B;
        #pragma unroll
        for (int ks = 0; ks < 4; ++ks) {
            const int kb = ks * 32 + lkh;
            uint32_t af[2][4];
            #pragma unroll
            for (int mt = 0; mt < 2; ++mt) {
                const int row = wm * 32 + mt * 16 + lrow;
                ldsm4(af[mt], Ab + row * 128 + (kb ^ ((row & 7) << 4)));
            }
            uint32_t bf[4][4];
            #pragma unroll
            for (int ng = 0; ng < 4; ++ng) {
                const int row = wn * 64 + ng * 16 + lrow;
                ldsm4(bf[ng], Bb + row * 128 + (kb ^ ((row & 7) << 4)));
            }
            #pragma unroll
            for (int mt = 0; mt < 2; ++mt)
                #pragma unroll
                for (int nt = 0; nt < 8; ++nt)
                    mma_tf32(acc[mt][nt], af[mt],
                             bf[nt >> 1][nt & 1], bf[nt >> 1][(nt & 1) + 2]);
        }
    };

    const int S = K / BK;

    ldgA(0); ldgB(0);
    stsA(0); stsB(0);
    __syncthreads();

    #pragma unroll 1
    for (int kt = 0; kt < S; ++kt) {
        const int nxt = kt + 1;
        if (nxt < S) { ldgA(nxt * BK); ldgB(nxt * BK); }
        compute(kt & 1);
        if (nxt < S) { stsA(nxt & 1); stsB(nxt & 1); }
        __syncthreads();
    }

    // epilogue: +bias, optional relu, float2 stores
    #pragma unroll
    for (int mt = 0; mt < 2; ++mt) {
        const int r = m0 + wm * 32 + mt * 16 + g;
        #pragma unroll
        for (int nt = 0; nt < 8; ++nt) {
            const int c = n0 + wn * 64 + nt * 8 + tg * 2;
            const float b0v = bias[c], b1v = bias[c + 1];
            float v0 = acc[mt][nt][0] + b0v;
            float v1 = acc[mt][nt][1] + b1v;
            float v2 = acc[mt][nt][2] + b0v;
            float v3 = acc[mt][nt][3] + b1v;
            if (RELU) {
                v0 = fmaxf(v0, 0.f); v1 = fmaxf(v1, 0.f);
                v2 = fmaxf(v2, 0.f); v3 = fmaxf(v3, 0.f);
            }
            float2 p0; p0.x = v0; p0.y = v1;
            float2 p1; p1.x = v2; p1.y = v3;
            *(float2*)(C + (size_t)r * ldc + c)       = p0;
            *(float2*)(C + (size_t)(r + 8) * ldc + c) = p1;
        }
    }
}

} // anonymous namespace

extern "C" void kernel_launch(void* const* d_in, const int* in_sizes, int n_in,
                              void* d_out, int out_size) {
    (void)in_sizes; (void)n_in; (void)out_size;
    const float* x  = (const float*)d_in[0];  // [B, M, DIN]
    const float* W1 = (const float*)d_in[1];  // [M, DIN, DH]
    const float* b1 = (const float*)d_in[2];  // [M, DH]
    const float* W2 = (const float*)d_in[3];  // [M, DH, DOUT]
    const float* b2 = (const float*)d_in[4];  // [M, DOUT]
    float* out = (float*)d_out;               // [B, M, DOUT]

    float* h = nullptr;
    cudaGetSymbolAddress((void**)&h, g_h);

    cudaFuncSetAttribute(gemm_tf32<true>,  cudaFuncAttributeMaxDynamicSharedMemorySize, SMEM_DYN);
    cudaFuncSetAttribute(gemm_tf32<false>, cudaFuncAttributeMaxDynamicSharedMemorySize, SMEM_DYN);

    dim3 blk(256);

    // Layer 1: per m, h[b, n] = relu(x[b,:] @ W1 + b1)
    dim3 g1(DH / BN, Bsz / BM, Msl);
    gemm_tf32<true><<<g1, blk, SMEM_DYN>>>(
        x, W1, b1, h, DIN,
        /*aBatch*/ (long)DIN,        /*lda*/ Msl * DIN,
        /*wBatch*/ (long)DIN * DH,   /*ldw*/ DH,
        /*biasBatch*/ (long)DH,
        /*cBatch*/ (long)Bsz * DH,   /*ldc*/ DH);

    // Layer 2: per m, out[b, n] = h[b,:] @ W2 + b2
    dim3 g2(DOUT / BN, Bsz / BM, Msl);
    gemm_tf32<false><<<g2, blk, SMEM_DYN>>>(
        h, W2, b2, out, DH,
        /*aBatch*/ (long)Bsz * DH,   /*lda*/ DH,
        /*wBatch*/ (long)DH * DOUT,  /*ldw*/ DOUT,
        /*biasBatch*/ (long)DOUT,
        /*cBatch*/ (long)DOUT,       /*ldc*/ Msl * DOUT);
}

// round 6
// speedup vs baseline: 1.3522x; 1.1625x over previous
#include <cuda_runtime.h>
#include <cstdint>

namespace {

constexpr int Bsz = 512, Msl = 32, DIN = 1024, DH = 4096, DOUT = 1024;
constexpr int BM = 128, BN = 128, BK = 32;
constexpr int TILE_B = 128 * BK * 4;      // 16 KB per operand tile
constexpr int STAGE  = 2 * TILE_B;        // A + B = 32 KB
constexpr int SMEM_DYN = 2 * STAGE;       // 2-stage ping-pong = 64 KB

// Intermediate h: [m][b][dh], stored tf32-rounded by layer-1 epilogue.
__device__ float g_h[(size_t)Bsz * Msl * DH];
// x pre-rounded to tf32 bits (pre-pass kernel).
__device__ float g_x_tf[(size_t)Bsz * Msl * DIN];

__device__ __forceinline__ uint32_t f2tf(float f) {
    uint32_t u; asm("cvt.rna.tf32.f32 %0, %1;" : "=r"(u) : "f"(f)); return u;
}
__device__ __forceinline__ uint32_t smem_u32(const void* p) {
    uint32_t a;
    asm("{ .reg .u64 t; cvta.to.shared.u64 t, %1; cvt.u32.u64 %0, t; }" : "=r"(a) : "l"(p));
    return a;
}
__device__ __forceinline__ void cp16(uint32_t dst, const void* src) {
    asm volatile("cp.async.cg.shared.global [%0], [%1], 16;" :: "r"(dst), "l"(src));
}
#define CP_COMMIT() asm volatile("cp.async.commit_group;" ::: "memory")
#define CP_WAIT0()  asm volatile("cp.async.wait_group 0;" ::: "memory")

__device__ __forceinline__ void ldsm4(uint32_t r[4], uint32_t addr) {
    asm volatile("ldmatrix.sync.aligned.m8n8.x4.shared.b16 {%0,%1,%2,%3}, [%4];"
                 : "=r"(r[0]), "=r"(r[1]), "=r"(r[2]), "=r"(r[3]) : "r"(addr));
}
__device__ __forceinline__ void mma_tf32(float acc[4], const uint32_t a[4],
                                         uint32_t b0, uint32_t b1) {
    asm volatile(
        "mma.sync.aligned.m16n8k8.row.col.f32.tf32.tf32.f32 "
        "{%0,%1,%2,%3}, {%4,%5,%6,%7}, {%8,%9}, {%0,%1,%2,%3};\n"
        : "+f"(acc[0]), "+f"(acc[1]), "+f"(acc[2]), "+f"(acc[3])
        : "r"(a[0]), "r"(a[1]), "r"(a[2]), "r"(a[3]), "r"(b0), "r"(b1));
}

// Pre-pass: round x to tf32 bits (vectorized).
__global__ void __launch_bounds__(256)
cvt_tf32(const float4* __restrict__ in, float4* __restrict__ out, int n4) {
    int i = blockIdx.x * blockDim.x + threadIdx.x;
    if (i < n4) {
        float4 v = in[i];
        float4 o;
        o.x = __uint_as_float(f2tf(v.x));
        o.y = __uint_as_float(f2tf(v.y));
        o.z = __uint_as_float(f2tf(v.z));
        o.w = __uint_as_float(f2tf(v.w));
        out[i] = o;
    }
}

// C[BM,BN] tile of A[*,K] x W[K,*] (+bias, optional ReLU), batched over blockIdx.z.
// A is PRE-ROUNDED tf32 bits in global, K-contiguous -> cp.async straight to smem.
// W rows are n-contiguous -> LDG + in-register 4x4 transpose + rna + permuted STS.
// ROUND_OUT: store C tf32-rounded (layer-1 h feeding layer-2's A side).
template<bool RELU, bool ROUND_OUT>
__global__ void __launch_bounds__(256, 2)
gemm_tf32(const float* __restrict__ Ag, const float* __restrict__ Wg,
          const float* __restrict__ biasg, float* __restrict__ Cg,
          int K,
          long aBatch, int lda, long wBatch, int ldw,
          long biasBatch, long cBatch, int ldc)
{
    extern __shared__ char sm[];
    const uint32_t sb = smem_u32(sm);

    const int tid  = threadIdx.x;
    const int lane = tid & 31, warp = tid >> 5;
    const int g = lane >> 2, tg = lane & 3;
    const int wm = warp & 3, wn = warp >> 2;          // 4 (m) x 2 (n) warps

    const int m0 = blockIdx.y * BM;
    const int n0 = blockIdx.x * BN;
    const float* A    = Ag    + (size_t)blockIdx.z * aBatch;
    const float* W    = Wg    + (size_t)blockIdx.z * wBatch;
    const float* bias = biasg + (size_t)blockIdx.z * biasBatch;
    float*       C    = Cg    + (size_t)blockIdx.z * cBatch;

    // A cp.async assignment: thread covers 4 rows x 16B
    const int a_kg = tid & 7;          // 16B group within 128B k-row
    const int a_r0 = tid >> 3;         // row r0 (+32 per it)
    // B LDG (coalesced): 4x4 block, k warp-constant
    const int b_n  = (tid & 31) * 4;   // n base of this thread's 4x4 block
    const int b_k0 = (tid >> 5) * 4;   // k base (warp-constant)

    // ldmatrix per-thread pieces
    const int lrow = lane & 15;
    const int lkh  = (lane >> 4) << 4;  // 0 or 16 bytes (k half)

    float acc[2][8][4];
    #pragma unroll
    for (int i = 0; i < 2; i++)
        #pragma unroll
        for (int j = 0; j < 8; j++)
            #pragma unroll
            for (int q = 0; q < 4; q++) acc[i][j][q] = 0.f;

    float4 rb[4];

    // A global->smem, no registers, no cvt (pre-rounded tf32 bits)
    auto cpA = [&](int k0, int buf) {
        const uint32_t base = sb + buf * STAGE;
        #pragma unroll
        for (int it = 0; it < 4; ++it) {
            const int r = a_r0 + it * 32;
            const uint32_t off = r * 128 + ((a_kg * 16) ^ ((r & 7) << 4));
            cp16(base + off, A + (size_t)(m0 + r) * lda + k0 + a_kg * 4);
        }
    };
    auto ldgB = [&](int k0) {
        const float* wp = W + (size_t)(k0 + b_k0) * ldw + n0 + b_n;
        #pragma unroll
        for (int j = 0; j < 4; ++j)
            rb[j] = *(const float4*)(wp + (size_t)j * ldw);
    };
    // 4x4 in-register transpose + rna; store order permuted per lane so each
    // 8-lane phase covers all 8 bank slots (row&7 = (lane&1)*4 + p).
    auto stsB = [&](int buf) {
        const uint32_t base = buf * STAGE + TILE_B;
        uint4 c[4];
        c[0].x = f2tf(rb[0].x); c[0].y = f2tf(rb[1].x); c[0].z = f2tf(rb[2].x); c[0].w = f2tf(rb[3].x);
        c[1].x = f2tf(rb[0].y); c[1].y = f2tf(rb[1].y); c[1].z = f2tf(rb[2].y); c[1].w = f2tf(rb[3].y);
        c[2].x = f2tf(rb[0].z); c[2].y = f2tf(rb[1].z); c[2].z = f2tf(rb[2].z); c[2].w = f2tf(rb[3].z);
        c[3].x = f2tf(rb[0].w); c[3].y = f2tf(rb[1].w); c[3].z = f2tf(rb[2].w); c[3].w = f2tf(rb[3].w);
        const int rot = (lane >> 1) & 3;
        #pragma unroll
        for (int j = 0; j < 4; ++j) {
            const int p = (j + rot) & 3;
            const int row = b_n + p;
            const uint32_t off = row * 128 + ((b_k0 * 4) ^ ((row & 7) << 4));
            *(uint4*)(sm + base + off) = c[p];
        }
    };

    auto compute = [&](int buf) {
        const uint32_t Ab = sb + buf * STAGE;
        const uint32_t Bb = Ab + TILE_B;
        #pragma unroll
        for (int ks = 0; ks < 4; ++ks) {
            const int kb = ks * 32 + lkh;
            uint32_t af[2][4];
            #pragma unroll
            for (int mt = 0; mt < 2; ++mt) {
                const int row = wm * 32 + mt * 16 + lrow;
                ldsm4(af[mt], Ab + row * 128 + (kb ^ ((row & 7) << 4)));
            }
            uint32_t bf[4][4];
            #pragma unroll
            for (int ng = 0; ng < 4; ++ng) {
                const int row = wn * 64 + ng * 16 + lrow;
                ldsm4(bf[ng], Bb + row * 128 + (kb ^ ((row & 7) << 4)));
            }
            #pragma unroll
            for (int mt = 0; mt < 2; ++mt)
                #pragma unroll
                for (int nt = 0; nt < 8; ++nt)
                    mma_tf32(acc[mt][nt], af[mt],
                             bf[nt >> 1][nt & 1], bf[nt >> 1][(nt & 1) + 2]);
        }
    };

    const int S = K / BK;

    cpA(0, 0); CP_COMMIT();
    ldgB(0);
    stsB(0);
    CP_WAIT0();
    __syncthreads();

    #pragma unroll 1
    for (int kt = 0; kt < S; ++kt) {
        const int nxt = kt + 1;
        if (nxt < S) { cpA(nxt * BK, nxt & 1); CP_COMMIT(); ldgB(nxt * BK); }
        compute(kt & 1);
        if (nxt < S) { stsB(nxt & 1); CP_WAIT0(); }
        __syncthreads();
    }

    // epilogue: +bias, optional relu, optional tf32 rounding, float2 stores
    #pragma unroll
    for (int mt = 0; mt < 2; ++mt) {
        const int r = m0 + wm * 32 + mt * 16 + g;
        #pragma unroll
        for (int nt = 0; nt < 8; ++nt) {
            const int c = n0 + wn * 64 + nt * 8 + tg * 2;
            const float b0v = bias[c], b1v = bias[c + 1];
            float v0 = acc[mt][nt][0] + b0v;
            float v1 = acc[mt][nt][1] + b1v;
            float v2 = acc[mt][nt][2] + b0v;
            float v3 = acc[mt][nt][3] + b1v;
            if (RELU) {
                v0 = fmaxf(v0, 0.f); v1 = fmaxf(v1, 0.f);
                v2 = fmaxf(v2, 0.f); v3 = fmaxf(v3, 0.f);
            }
            if (ROUND_OUT) {
                v0 = __uint_as_float(f2tf(v0));
                v1 = __uint_as_float(f2tf(v1));
                v2 = __uint_as_float(f2tf(v2));
                v3 = __uint_as_float(f2tf(v3));
            }
            float2 p0; p0.x = v0; p0.y = v1;
            float2 p1; p1.x = v2; p1.y = v3;
            *(float2*)(C + (size_t)r * ldc + c)       = p0;
            *(float2*)(C + (size_t)(r + 8) * ldc + c) = p1;
        }
    }
}

} // anonymous namespace

extern "C" void kernel_launch(void* const* d_in, const int* in_sizes, int n_in,
                              void* d_out, int out_size) {
    (void)in_sizes; (void)n_in; (void)out_size;
    const float* x  = (const float*)d_in[0];  // [B, M, DIN]
    const float* W1 = (const float*)d_in[1];  // [M, DIN, DH]
    const float* b1 = (const float*)d_in[2];  // [M, DH]
    const float* W2 = (const float*)d_in[3];  // [M, DH, DOUT]
    const float* b2 = (const float*)d_in[4];  // [M, DOUT]
    float* out = (float*)d_out;               // [B, M, DOUT]

    float* h = nullptr;
    cudaGetSymbolAddress((void**)&h, g_h);
    float* x_tf = nullptr;
    cudaGetSymbolAddress((void**)&x_tf, g_x_tf);

    cudaFuncSetAttribute(gemm_tf32<true, true>,   cudaFuncAttributeMaxDynamicSharedMemorySize, SMEM_DYN);
    cudaFuncSetAttribute(gemm_tf32<false, false>, cudaFuncAttributeMaxDynamicSharedMemorySize, SMEM_DYN);

    // Pre-pass: x -> tf32 bits (~16 us)
    {
        const int n4 = Bsz * Msl * DIN / 4;
        cvt_tf32<<<(n4 + 255) / 256, 256>>>((const float4*)x, (float4*)x_tf, n4);
    }

    dim3 blk(256);

    // Layer 1: per m, h[b, n] = rna(relu(x[b,:] @ W1 + b1))
    dim3 g1(DH / BN, Bsz / BM, Msl);
    gemm_tf32<true, true><<<g1, blk, SMEM_DYN>>>(
        x_tf, W1, b1, h, DIN,
        /*aBatch*/ (long)DIN,        /*lda*/ Msl * DIN,
        /*wBatch*/ (long)DIN * DH,   /*ldw*/ DH,
        /*biasBatch*/ (long)DH,
        /*cBatch*/ (long)Bsz * DH,   /*ldc*/ DH);

    // Layer 2: per m, out[b, n] = h[b,:] @ W2 + b2
    dim3 g2(DOUT / BN, Bsz / BM, Msl);
    gemm_tf32<false, false><<<g2, blk, SMEM_DYN>>>(
        h, W2, b2, out, DH,
        /*aBatch*/ (long)Bsz * DH,   /*lda*/ DH,
        /*wBatch*/ (long)DH * DOUT,  /*ldw*/ DOUT,
        /*biasBatch*/ (long)DOUT,
        /*cBatch*/ (long)DOUT,       /*ldc*/ Msl * DOUT);
}